// round 4
// baseline (speedup 1.0000x reference)
#include <cuda_runtime.h>

// Problem constants
#define DIM   192
#define NB    2
#define KVOL_INV (1.0f / 27.0f)
#define SMOOTH_DR 1e-5f
#define N_TOTAL (2.0 * 192.0 * 192.0 * 192.0)

// Tiling
#define BX      32          // threads / tile width in x (fastest dim)
#define BY      16          // threads in y (incl. 2 halo rows)
#define Y_INNER 14          // output rows per block in y
#define ZCHUNK  24          // output planes per block in z

__device__ double g_acc;

__global__ void zero_acc_kernel() { g_acc = 0.0; }

__global__ void finalize_kernel(float* out) {
    out[0] = (float)(-g_acc / N_TOTAL);
}

__global__ __launch_bounds__(BX * BY) void ncc_kernel(
    const float* __restrict__ pred,
    const float* __restrict__ targ)
{
    // smem: 5 quantities x 16 rows x 32 cols (zx-sums per plane)
    __shared__ float s[5][BY][BX];

    const int tx = threadIdx.x;
    const int ty = threadIdx.y;
    const int x  = blockIdx.x * BX + tx;                 // always < 192
    const int y  = blockIdx.y * Y_INNER + ty - 1;        // -1 .. 196
    const int zb = blockIdx.z;                           // 0..15
    const int b  = zb >> 3;                              // batch
    const int zc = (zb & 7) * ZCHUNK;                    // chunk base plane

    const bool yin = (y >= 0 && y < DIM);
    const size_t vol_base = (size_t)b * DIM * DIM * DIM;

    // z-ring of the five x-sums (I, J, II, JJ, IJ) for 3 planes
    float ring[3][5];
#pragma unroll
    for (int i = 0; i < 3; i++)
#pragma unroll
        for (int q = 0; q < 5; q++) ring[i][q] = 0.0f;

    float acc = 0.0f;

    // Sweep 27 planes: zp = zc-2 .. zc+24. Output plane z = zp-1 for it >= 3.
    for (int itc = 0; itc < 9; ++itc) {
#pragma unroll
        for (int sub = 0; sub < 3; ++sub) {
            const int it = itc * 3 + sub;
            const int zp = zc - 2 + it;

            float xsI = 0.f, xsJ = 0.f, xsII = 0.f, xsJJ = 0.f, xsIJ = 0.f;
            if (zp >= 0 && zp < DIM && yin) {
                const size_t rb = vol_base + ((size_t)zp * DIM + y) * DIM;
                const float i0 = pred[rb + x];
                const float j0 = targ[rb + x];
                float im = 0.f, jm = 0.f, ip = 0.f, jp = 0.f;
                if (x > 0)       { im = pred[rb + x - 1]; jm = targ[rb + x - 1]; }
                if (x < DIM - 1) { ip = pred[rb + x + 1]; jp = targ[rb + x + 1]; }
                xsI  = im + i0 + ip;
                xsJ  = jm + j0 + jp;
                xsII = im * im + i0 * i0 + ip * ip;
                xsJJ = jm * jm + j0 * j0 + jp * jp;
                xsIJ = im * jm + i0 * j0 + ip * jp;
            }
            // slot = it % 3 = sub (static under unroll -> registers)
            ring[sub][0] = xsI;  ring[sub][1] = xsJ;  ring[sub][2] = xsII;
            ring[sub][3] = xsJJ; ring[sub][4] = xsIJ;

            if (it >= 3) {   // uniform across block
                // z-sum centered at z = zp-1
                float zs[5];
#pragma unroll
                for (int q = 0; q < 5; q++)
                    zs[q] = ring[0][q] + ring[1][q] + ring[2][q];

                __syncthreads();   // protect smem from previous iteration's reads
#pragma unroll
                for (int q = 0; q < 5; q++) s[q][ty][tx] = zs[q];
                __syncthreads();

                if (ty >= 1 && ty <= Y_INNER && y < DIM) {
                    float S[5];
#pragma unroll
                    for (int q = 0; q < 5; q++)
                        S[q] = zs[q] + s[q][ty - 1][tx] + s[q][ty + 1][tx];

                    const float SI = S[0], SJ = S[1], SII = S[2], SJJ = S[3], SIJ = S[4];
                    const float cross = SIJ - SI * SJ * KVOL_INV;
                    const float pvar  = SII - SI * SI * KVOL_INV;
                    const float tvar  = SJJ - SJ * SJ * KVOL_INV;
                    acc += (cross * cross) / (tvar * pvar + SMOOTH_DR);
                }
            }
        }
    }

    // Block reduction into g_acc
    __syncthreads();
    float* red = &s[0][0][0];   // reuse smem (2560 floats >= 512)
    const int tid = ty * BX + tx;
    red[tid] = acc;
    __syncthreads();
#pragma unroll
    for (int stride = (BX * BY) / 2; stride > 0; stride >>= 1) {
        if (tid < stride) red[tid] += red[tid + stride];
        __syncthreads();
    }
    if (tid == 0) atomicAdd(&g_acc, (double)red[0]);
}

extern "C" void kernel_launch(void* const* d_in, const int* in_sizes, int n_in,
                              void* d_out, int out_size) {
    const float* pred = (const float*)d_in[0];
    const float* targ = (const float*)d_in[1];
    float* out = (float*)d_out;

    zero_acc_kernel<<<1, 1>>>();

    dim3 block(BX, BY);
    dim3 grid(DIM / BX,                               // 6
              (DIM + Y_INNER - 1) / Y_INNER,          // 14
              NB * (DIM / ZCHUNK));                   // 16
    ncc_kernel<<<grid, block>>>(pred, targ);

    finalize_kernel<<<1, 1>>>(out);
}